// round 5
// baseline (speedup 1.0000x reference)
#include <cuda_runtime.h>
#include <math.h>
#include <stdint.h>

#define T_DIM 512
#define B_DIM 128
#define D_IN  128
#define H_DIM 512
#define R_DIM (T_DIM * B_DIM)   // 65536 rows for phase-1 GEMM

// sW[16][516] + sH[32][516] floats, padded +4 for bank-conflict-free access
#define WPAD 516
#define RNN_SMEM_BYTES ((16 * WPAD + 32 * WPAD) * 4)

// ---------------- scratch (device globals: allocation-free) ----------------
__device__ __align__(16) float g_xp[(size_t)R_DIM * H_DIM];  // 128 MB: xp = x@W_ih^T + b_ih
__device__ int g_count;                                       // single barrier arrive counter

// ---------------- acquire/release helpers ----------------
__device__ __forceinline__ int ld_acq(const int* p) {
    int v;
    asm volatile("ld.global.acquire.gpu.b32 %0, [%1];" : "=r"(v) : "l"(p));
    return v;
}
__device__ __forceinline__ void red_rel_add(int* p, int v) {
    asm volatile("red.release.gpu.global.add.s32 [%0], %1;" :: "l"(p), "r"(v));
}

// ---------------- phase 1: xp = x @ W_ih^T + b_ih ----------------
__global__ void xp_kernel(const float* __restrict__ x,
                          const float* __restrict__ W,
                          const float* __restrict__ bias) {
    __shared__ float sA[64][68];   // sA[k][m]
    __shared__ float sB[64][68];   // sB[k][n]

    const int tid = threadIdx.x;
    if (blockIdx.x == 0 && blockIdx.y == 0 && tid == 0) g_count = 0;

    const int tx = tid & 15;
    const int ty = tid >> 4;
    const int rbase = blockIdx.x * 64;
    const int cbase = blockIdx.y * 64;

    float acc[4][4];
#pragma unroll
    for (int i = 0; i < 4; i++)
#pragma unroll
        for (int j = 0; j < 4; j++) acc[i][j] = 0.0f;

    for (int kb = 0; kb < D_IN; kb += 64) {
#pragma unroll
        for (int i = 0; i < 4; i++) {
            int idx = i * 256 + tid;
            int row = idx >> 4;
            int k4  = idx & 15;
            float4 v = *(const float4*)&x[(size_t)(rbase + row) * D_IN + kb + k4 * 4];
            sA[k4 * 4 + 0][row] = v.x; sA[k4 * 4 + 1][row] = v.y;
            sA[k4 * 4 + 2][row] = v.z; sA[k4 * 4 + 3][row] = v.w;
            float4 w = *(const float4*)&W[(size_t)(cbase + row) * D_IN + kb + k4 * 4];
            sB[k4 * 4 + 0][row] = w.x; sB[k4 * 4 + 1][row] = w.y;
            sB[k4 * 4 + 2][row] = w.z; sB[k4 * 4 + 3][row] = w.w;
        }
        __syncthreads();
#pragma unroll
        for (int k = 0; k < 64; k++) {
            float4 a = *(const float4*)&sA[k][ty * 4];
            float4 b = *(const float4*)&sB[k][tx * 4];
            acc[0][0] = fmaf(a.x, b.x, acc[0][0]); acc[0][1] = fmaf(a.x, b.y, acc[0][1]);
            acc[0][2] = fmaf(a.x, b.z, acc[0][2]); acc[0][3] = fmaf(a.x, b.w, acc[0][3]);
            acc[1][0] = fmaf(a.y, b.x, acc[1][0]); acc[1][1] = fmaf(a.y, b.y, acc[1][1]);
            acc[1][2] = fmaf(a.y, b.z, acc[1][2]); acc[1][3] = fmaf(a.y, b.w, acc[1][3]);
            acc[2][0] = fmaf(a.z, b.x, acc[2][0]); acc[2][1] = fmaf(a.z, b.y, acc[2][1]);
            acc[2][2] = fmaf(a.z, b.z, acc[2][2]); acc[2][3] = fmaf(a.z, b.w, acc[2][3]);
            acc[3][0] = fmaf(a.w, b.x, acc[3][0]); acc[3][1] = fmaf(a.w, b.y, acc[3][1]);
            acc[3][2] = fmaf(a.w, b.z, acc[3][2]); acc[3][3] = fmaf(a.w, b.w, acc[3][3]);
        }
        __syncthreads();
    }

    float4 bj = *(const float4*)&bias[cbase + tx * 4];
#pragma unroll
    for (int i = 0; i < 4; i++) {
        float4 o;
        o.x = acc[i][0] + bj.x; o.y = acc[i][1] + bj.y;
        o.z = acc[i][2] + bj.z; o.w = acc[i][3] + bj.w;
        *(float4*)&g_xp[(size_t)(rbase + ty * 4 + i) * H_DIM + cbase + tx * 4] = o;
    }
}

// ---------------- phase 2: persistent recurrence ----------------
// 128 CTAs x 512 threads (4 warps/SMSP for latency hiding). CTA tile: 32 x 16.
// One output per thread. Warp tile 4 rows x 8 cols:
//   per 4-k iter: 1 LDS.128 h (broadcast) + 1 LDS.128 w + 4 FFMA.
// Each warp stages 2 h-rows via 8 front-batched LDG.128/lane, one __syncthreads.
__global__ __launch_bounds__(512, 1)
void rnn_kernel(const float* __restrict__ Whh,
                const float* __restrict__ bhh,
                float* __restrict__ out) {
    extern __shared__ float smem[];
    float* sW = smem;               // [16][WPAD]
    float* sH = smem + 16 * WPAD;   // [32][WPAD]

    const int tid  = threadIdx.x;
    const int lane = tid & 31;
    const int wrp  = tid >> 5;             // 0..15
    const int bm = blockIdx.x & 3;         // 4 m-tiles of 32 rows
    const int bn = blockIdx.x >> 2;        // 32 n-tiles of 16 cols
    const int mbase = bm * 32;
    const int nbase = bn * 16;

    // warp tile: rows 4*(wrp>>1)..+3, cols 8*(wrp&1)..+7
    const int row = 4 * (wrp >> 1) + (lane >> 3);   // 0..31
    const int col = 8 * (wrp & 1) + (lane & 7);     // 0..15

    // load W slice transposed into sW[col][k] (one time)
    for (int idx = tid; idx < 16 * 512; idx += 512) {
        int j = idx >> 9;          // col 0..15
        int k = idx & 511;
        sW[j * WPAD + k] = Whh[(size_t)(nbase + j) * H_DIM + k];
    }
    const float bias = bhh[nbase + col];
    __syncthreads();

    float* const hlast = out + (size_t)T_DIM * B_DIM * H_DIM;
    const float* hp = &sH[(size_t)row * WPAD];
    const float* wp = &sW[(size_t)col * WPAD];

    // staging geometry: warp stages rows 2*wrp, 2*wrp+1 (2x512 floats = 256 float4)
    const int stg_row0 = wrp * 2;
    float* const sH_w = &sH[(size_t)stg_row0 * WPAD];

    for (int t = 0; t < T_DIM; ++t) {
        // prefetch xp for this step EARLY
        const size_t xbase = ((size_t)t * B_DIM + mbase + row) * H_DIM + nbase + col;
        const float xpv = __ldcg(&g_xp[xbase]);

        float acc = 0.0f;

        if (t > 0) {
            const float* hprev = out + (size_t)(t - 1) * B_DIM * H_DIM
                               + (size_t)(mbase + stg_row0) * H_DIM;

            // stage this warp's 2 rows: 8 front-batched LDG.128 per lane
            float4 pre[8];
#pragma unroll
            for (int i = 0; i < 8; i++) {
                int f = i * 32 + lane;                 // 0..255
                pre[i] = __ldcg((const float4*)hprev + f);
            }
#pragma unroll
            for (int i = 0; i < 8; i++) {
                int f  = i * 32 + lane;
                int r  = f >> 7;                        // 0..1
                int c4 = f & 127;
                *(float4*)&sH_w[(size_t)r * WPAD + c4 * 4] = pre[i];
            }
            __syncthreads();   // other warps read rows staged here

#pragma unroll 16
            for (int k = 0; k < H_DIM; k += 4) {
                float4 h = *(const float4*)(hp + k);
                float4 w = *(const float4*)(wp + k);
                acc = fmaf(h.x, w.x, acc);
                acc = fmaf(h.y, w.y, acc);
                acc = fmaf(h.z, w.z, acc);
                acc = fmaf(h.w, w.w, acc);
            }
        }

        // epilogue: add xp + bias, tanh, store h_seq[t]
        float* hout = out + (size_t)t * B_DIM * H_DIM;
        float v = tanhf(acc + xpv + bias);
        const size_t obase = (size_t)(mbase + row) * H_DIM + nbase + col;
        hout[obase] = v;
        if (t == T_DIM - 1) hlast[obase] = v;

        // grid barrier (skip after final step): single counter, single poller per CTA
        if (t < T_DIM - 1) {
            __syncthreads();               // all stores of this CTA's tile issued
            if (tid == 0) {
                red_rel_add(&g_count, 1);  // release: orders the h stores
                const int target = 128 * (t + 1);
                while (ld_acq(&g_count) < target) { __nanosleep(16); }
            }
            __syncthreads();               // broadcast barrier pass to CTA
        }
    }
}

// ---------------- launch ----------------
extern "C" void kernel_launch(void* const* d_in, const int* in_sizes, int n_in,
                              void* d_out, int out_size) {
    const float* x    = (const float*)d_in[0];
    const float* W_ih = (const float*)d_in[1];
    const float* b_ih = (const float*)d_in[2];
    const float* W_hh = (const float*)d_in[3];
    const float* b_hh = (const float*)d_in[4];
    float* out = (float*)d_out;

    cudaFuncSetAttribute(rnn_kernel, cudaFuncAttributeMaxDynamicSharedMemorySize,
                         RNN_SMEM_BYTES);

    xp_kernel<<<dim3(R_DIM / 64, H_DIM / 64), 256>>>(x, W_ih, b_ih);
    rnn_kernel<<<128, 512, RNN_SMEM_BYTES>>>(W_hh, b_hh, out);
}

// round 6
// speedup vs baseline: 1.0558x; 1.0558x over previous
#include <cuda_runtime.h>
#include <math.h>
#include <stdint.h>

#define T_DIM 512
#define B_DIM 128
#define D_IN  128
#define H_DIM 512
#define R_DIM (T_DIM * B_DIM)   // 65536 rows for phase-1 GEMM

#define WPAD 516                 // +4 floats pad: 2064B row stride -> bank-distinct
#define NGROUPS 16               // 16 independent groups of 8 CTAs / 8 batch rows
// sW[64][WPAD] + sH[8][WPAD]
#define RNN_SMEM_BYTES ((64 * WPAD + 8 * WPAD) * 4)

// ---------------- scratch (device globals: allocation-free) ----------------
__device__ __align__(16) float g_xp[(size_t)R_DIM * H_DIM];  // xp = x@W_ih^T + b_ih
__device__ int g_counts[NGROUPS * 128];                       // per-group counters, 512B apart

// ---------------- acquire/release helpers ----------------
__device__ __forceinline__ int ld_acq(const int* p) {
    int v;
    asm volatile("ld.global.acquire.gpu.b32 %0, [%1];" : "=r"(v) : "l"(p));
    return v;
}
__device__ __forceinline__ void red_rel_add(int* p, int v) {
    asm volatile("red.release.gpu.global.add.s32 [%0], %1;" :: "l"(p), "r"(v));
}

// ---------------- phase 1: xp = x @ W_ih^T + b_ih ----------------
// grid (1024, 8), block 256, 64x64 tiles. Block (0,0) also resets group counters.
__global__ void xp_kernel(const float* __restrict__ x,
                          const float* __restrict__ W,
                          const float* __restrict__ bias) {
    __shared__ float sA[64][68];   // sA[k][m]
    __shared__ float sB[64][68];   // sB[k][n]

    const int tid = threadIdx.x;
    if (blockIdx.x == 0 && blockIdx.y == 0 && tid < NGROUPS) g_counts[tid * 128] = 0;

    const int tx = tid & 15;
    const int ty = tid >> 4;
    const int rbase = blockIdx.x * 64;
    const int cbase = blockIdx.y * 64;

    float acc[4][4];
#pragma unroll
    for (int i = 0; i < 4; i++)
#pragma unroll
        for (int j = 0; j < 4; j++) acc[i][j] = 0.0f;

    for (int kb = 0; kb < D_IN; kb += 64) {
#pragma unroll
        for (int i = 0; i < 4; i++) {
            int idx = i * 256 + tid;
            int row = idx >> 4;
            int k4  = idx & 15;
            float4 v = *(const float4*)&x[(size_t)(rbase + row) * D_IN + kb + k4 * 4];
            sA[k4 * 4 + 0][row] = v.x; sA[k4 * 4 + 1][row] = v.y;
            sA[k4 * 4 + 2][row] = v.z; sA[k4 * 4 + 3][row] = v.w;
            float4 w = *(const float4*)&W[(size_t)(cbase + row) * D_IN + kb + k4 * 4];
            sB[k4 * 4 + 0][row] = w.x; sB[k4 * 4 + 1][row] = w.y;
            sB[k4 * 4 + 2][row] = w.z; sB[k4 * 4 + 3][row] = w.w;
        }
        __syncthreads();
#pragma unroll
        for (int k = 0; k < 64; k++) {
            float4 a = *(const float4*)&sA[k][ty * 4];
            float4 b = *(const float4*)&sB[k][tx * 4];
            acc[0][0] = fmaf(a.x, b.x, acc[0][0]); acc[0][1] = fmaf(a.x, b.y, acc[0][1]);
            acc[0][2] = fmaf(a.x, b.z, acc[0][2]); acc[0][3] = fmaf(a.x, b.w, acc[0][3]);
            acc[1][0] = fmaf(a.y, b.x, acc[1][0]); acc[1][1] = fmaf(a.y, b.y, acc[1][1]);
            acc[1][2] = fmaf(a.y, b.z, acc[1][2]); acc[1][3] = fmaf(a.y, b.w, acc[1][3]);
            acc[2][0] = fmaf(a.z, b.x, acc[2][0]); acc[2][1] = fmaf(a.z, b.y, acc[2][1]);
            acc[2][2] = fmaf(a.z, b.z, acc[2][2]); acc[2][3] = fmaf(a.z, b.w, acc[2][3]);
            acc[3][0] = fmaf(a.w, b.x, acc[3][0]); acc[3][1] = fmaf(a.w, b.y, acc[3][1]);
            acc[3][2] = fmaf(a.w, b.z, acc[3][2]); acc[3][3] = fmaf(a.w, b.w, acc[3][3]);
        }
        __syncthreads();
    }

    float4 bj = *(const float4*)&bias[cbase + tx * 4];
#pragma unroll
    for (int i = 0; i < 4; i++) {
        float4 o;
        o.x = acc[i][0] + bj.x; o.y = acc[i][1] + bj.y;
        o.z = acc[i][2] + bj.z; o.w = acc[i][3] + bj.w;
        *(float4*)&g_xp[(size_t)(rbase + ty * 4 + i) * H_DIM + cbase + tx * 4] = o;
    }
}

// ---------------- phase 2: grouped persistent recurrence ----------------
// The recurrence is independent per batch row. 16 groups x 8 CTAs; group g owns
// batch rows 8g..8g+7 and NEVER syncs with other groups. CTA c in a group keeps
// W cols [64c,64c+64) resident in SMEM and computes an 8x64 chunk per step.
// Exchange via h_seq in L2 + an 8-arrival per-group counter barrier.
__global__ __launch_bounds__(512, 1)
void rnn_kernel(const float* __restrict__ Whh,
                const float* __restrict__ bhh,
                float* __restrict__ out) {
    extern __shared__ float smem[];
    float* sW = smem;              // [64][WPAD] : W slice, k-major
    float* sH = smem + 64 * WPAD;  // [8][WPAD]  : group's 8 h rows

    const int tid  = threadIdx.x;
    const int lane = tid & 31;
    const int wrp  = tid >> 5;               // 0..15
    const int grp  = blockIdx.x >> 3;        // 0..15
    const int c    = blockIdx.x & 7;         // 0..7  : W-column slice
    const int rowbase = grp * 8;             // first batch row of this group
    const int colbase = c * 64;              // first hidden col of this CTA

    // warp tile: 4 batch rows x 8 cols  (wrp = jg*2 + bg)
    const int b_loc = 4 * (wrp & 1) + (lane >> 3);   // 0..7
    const int j_loc = 8 * (wrp >> 1) + (lane & 7);   // 0..63

    // load W slice into sW[j][k] (one time; same slice for all 16 groups -> L2 hits)
    for (int i = 0; i < 64; i++) {
        int idx = i * 512 + tid;
        int jl = idx >> 9;
        int k  = idx & 511;
        sW[jl * WPAD + k] = Whh[(size_t)(colbase + jl) * H_DIM + k];
    }
    const float bias = bhh[colbase + j_loc];
    __syncthreads();

    float* const hlast = out + (size_t)T_DIM * B_DIM * H_DIM;
    const float* hb = &sH[(size_t)b_loc * WPAD];
    const float* wj = &sW[(size_t)j_loc * WPAD];
    int* const cnt = &g_counts[grp * 128];

    for (int t = 0; t < T_DIM; ++t) {
        // prefetch xp early (latency hidden under compute)
        const float xpv = __ldcg(&g_xp[((size_t)t * B_DIM + rowbase + b_loc) * H_DIM
                                       + colbase + j_loc]);

        float acc0 = 0.0f, acc1 = 0.0f;

        if (t > 0) {
            // stage group's 8 h rows (16KB contiguous): 2 coalesced LDG.128/thread
            const float4* src = (const float4*)(out + (size_t)(t - 1) * B_DIM * H_DIM
                                                + (size_t)rowbase * H_DIM);
            float4 p0 = __ldcg(src + tid);
            float4 p1 = __ldcg(src + 512 + tid);
            {
                int f0 = tid,        r0s = f0 >> 7, c0s = f0 & 127;
                int f1 = 512 + tid,  r1s = f1 >> 7, c1s = f1 & 127;
                *(float4*)&sH[(size_t)r0s * WPAD + c0s * 4] = p0;
                *(float4*)&sH[(size_t)r1s * WPAD + c1s * 4] = p1;
            }
            __syncthreads();

            // dual-accumulator dot product: k and k+256 halves
#pragma unroll 16
            for (int k = 0; k < 256; k += 4) {
                float4 h0 = *(const float4*)(hb + k);
                float4 w0 = *(const float4*)(wj + k);
                float4 h1 = *(const float4*)(hb + k + 256);
                float4 w1 = *(const float4*)(wj + k + 256);
                acc0 = fmaf(h0.x, w0.x, acc0); acc1 = fmaf(h1.x, w1.x, acc1);
                acc0 = fmaf(h0.y, w0.y, acc0); acc1 = fmaf(h1.y, w1.y, acc1);
                acc0 = fmaf(h0.z, w0.z, acc0); acc1 = fmaf(h1.z, w1.z, acc1);
                acc0 = fmaf(h0.w, w0.w, acc0); acc1 = fmaf(h1.w, w1.w, acc1);
            }
        }

        // epilogue: tanh + store h_seq[t]
        float v = tanhf(acc0 + acc1 + xpv + bias);
        const size_t obase = (size_t)(rowbase + b_loc) * H_DIM + colbase + j_loc;
        out[(size_t)t * B_DIM * H_DIM + obase] = v;
        if (t == T_DIM - 1) hlast[obase] = v;

        // per-group barrier (8 arrivals on own counter; skip after final step)
        if (t < T_DIM - 1) {
            __syncthreads();               // all chunk stores issued
            if (tid == 0) {
                red_rel_add(cnt, 1);       // release: orders the h stores
                const int target = 8 * (t + 1);
                while (ld_acq(cnt) < target) { __nanosleep(16); }
            }
            __syncthreads();               // broadcast barrier pass
        }
    }
}

// ---------------- launch ----------------
extern "C" void kernel_launch(void* const* d_in, const int* in_sizes, int n_in,
                              void* d_out, int out_size) {
    const float* x    = (const float*)d_in[0];
    const float* W_ih = (const float*)d_in[1];
    const float* b_ih = (const float*)d_in[2];
    const float* W_hh = (const float*)d_in[3];
    const float* b_hh = (const float*)d_in[4];
    float* out = (float*)d_out;

    cudaFuncSetAttribute(rnn_kernel, cudaFuncAttributeMaxDynamicSharedMemorySize,
                         RNN_SMEM_BYTES);

    xp_kernel<<<dim3(R_DIM / 64, H_DIM / 64), 256>>>(x, W_ih, b_ih);
    rnn_kernel<<<128, 512, RNN_SMEM_BYTES>>>(W_hh, b_hh, out);
}

// round 7
// speedup vs baseline: 2.0972x; 1.9864x over previous
#include <cuda_runtime.h>
#include <math.h>
#include <stdint.h>

#define T_DIM 512
#define B_DIM 128
#define D_IN  128
#define H_DIM 512
#define R_DIM (T_DIM * B_DIM)

// ---- phase-2 geometry: 8 row-groups x 16 col-CTAs ----
#define GROUPS 8           // groups of 16 batch rows
#define CTAS_PER_GROUP 16  // 512 cols / 32 per CTA
#define ROWS_PER_GROUP 16
#define COLS_PER_CTA 32

// SMEM layout (floats), pad 516 (= 4 mod 32 -> conflict-free frag reads)
#define APAD 516
#define AHI_OFF 0
#define ALO_OFF (16 * APAD)                 // 8256
#define BHI_OFF (2 * 16 * APAD)             // 16512
#define BLO_OFF (BHI_OFF + 32 * APAD)       // 33024
#define RED_OFF (BLO_OFF + 32 * APAD)       // 49536 ; red[8][16][33]
#define RED_WSTRIDE (16 * 33)               // 528
#define SMEM_FLOATS (RED_OFF + 8 * RED_WSTRIDE)   // 53760
#define RNN_SMEM_BYTES (SMEM_FLOATS * 4)          // 215040

// ---------------- scratch (device globals: allocation-free) ----------------
__device__ __align__(16) float g_xp[(size_t)R_DIM * H_DIM];
__device__ int g_counts[GROUPS * 128];   // per-group counters, 512B apart

// ---------------- helpers ----------------
__device__ __forceinline__ int ld_acq(const int* p) {
    int v;
    asm volatile("ld.global.acquire.gpu.b32 %0, [%1];" : "=r"(v) : "l"(p));
    return v;
}
__device__ __forceinline__ void red_rel_add(int* p, int v) {
    asm volatile("red.release.gpu.global.add.s32 [%0], %1;" :: "l"(p), "r"(v));
}
__device__ __forceinline__ uint32_t f2tf32(float x) {
    uint32_t r;
    asm("cvt.rna.tf32.f32 %0, %1;" : "=r"(r) : "f"(x));
    return r;
}
__device__ __forceinline__ void mma_tf32(float* d, uint32_t a0, uint32_t a1,
                                         uint32_t a2, uint32_t a3,
                                         uint32_t b0, uint32_t b1) {
    asm volatile(
        "mma.sync.aligned.m16n8k8.row.col.f32.tf32.tf32.f32 "
        "{%0,%1,%2,%3}, {%4,%5,%6,%7}, {%8,%9}, {%0,%1,%2,%3};"
        : "+f"(d[0]), "+f"(d[1]), "+f"(d[2]), "+f"(d[3])
        : "r"(a0), "r"(a1), "r"(a2), "r"(a3), "r"(b0), "r"(b1));
}

// ---------------- phase 1: xp = x @ W_ih^T + b_ih (unchanged) ----------------
__global__ void xp_kernel(const float* __restrict__ x,
                          const float* __restrict__ W,
                          const float* __restrict__ bias) {
    __shared__ float sA[64][68];
    __shared__ float sB[64][68];

    const int tid = threadIdx.x;
    if (blockIdx.x == 0 && blockIdx.y == 0 && tid < GROUPS) g_counts[tid * 128] = 0;

    const int tx = tid & 15;
    const int ty = tid >> 4;
    const int rbase = blockIdx.x * 64;
    const int cbase = blockIdx.y * 64;

    float acc[4][4];
#pragma unroll
    for (int i = 0; i < 4; i++)
#pragma unroll
        for (int j = 0; j < 4; j++) acc[i][j] = 0.0f;

    for (int kb = 0; kb < D_IN; kb += 64) {
#pragma unroll
        for (int i = 0; i < 4; i++) {
            int idx = i * 256 + tid;
            int row = idx >> 4;
            int k4  = idx & 15;
            float4 v = *(const float4*)&x[(size_t)(rbase + row) * D_IN + kb + k4 * 4];
            sA[k4 * 4 + 0][row] = v.x; sA[k4 * 4 + 1][row] = v.y;
            sA[k4 * 4 + 2][row] = v.z; sA[k4 * 4 + 3][row] = v.w;
            float4 w = *(const float4*)&W[(size_t)(cbase + row) * D_IN + kb + k4 * 4];
            sB[k4 * 4 + 0][row] = w.x; sB[k4 * 4 + 1][row] = w.y;
            sB[k4 * 4 + 2][row] = w.z; sB[k4 * 4 + 3][row] = w.w;
        }
        __syncthreads();
#pragma unroll
        for (int k = 0; k < 64; k++) {
            float4 a = *(const float4*)&sA[k][ty * 4];
            float4 b = *(const float4*)&sB[k][tx * 4];
            acc[0][0] = fmaf(a.x, b.x, acc[0][0]); acc[0][1] = fmaf(a.x, b.y, acc[0][1]);
            acc[0][2] = fmaf(a.x, b.z, acc[0][2]); acc[0][3] = fmaf(a.x, b.w, acc[0][3]);
            acc[1][0] = fmaf(a.y, b.x, acc[1][0]); acc[1][1] = fmaf(a.y, b.y, acc[1][1]);
            acc[1][2] = fmaf(a.y, b.z, acc[1][2]); acc[1][3] = fmaf(a.y, b.w, acc[1][3]);
            acc[2][0] = fmaf(a.z, b.x, acc[2][0]); acc[2][1] = fmaf(a.z, b.y, acc[2][1]);
            acc[2][2] = fmaf(a.z, b.z, acc[2][2]); acc[2][3] = fmaf(a.z, b.w, acc[2][3]);
            acc[3][0] = fmaf(a.w, b.x, acc[3][0]); acc[3][1] = fmaf(a.w, b.y, acc[3][1]);
            acc[3][2] = fmaf(a.w, b.z, acc[3][2]); acc[3][3] = fmaf(a.w, b.w, acc[3][3]);
        }
        __syncthreads();
    }

    float4 bj = *(const float4*)&bias[cbase + tx * 4];
#pragma unroll
    for (int i = 0; i < 4; i++) {
        float4 o;
        o.x = acc[i][0] + bj.x; o.y = acc[i][1] + bj.y;
        o.z = acc[i][2] + bj.z; o.w = acc[i][3] + bj.w;
        *(float4*)&g_xp[(size_t)(rbase + ty * 4 + i) * H_DIM + cbase + tx * 4] = o;
    }
}

// ---------------- phase 2: 3xTF32 tensor-core recurrence ----------------
// CTA = 16 batch rows x 32 cols; 8 warps k-split (k64 each), warp computes the
// full m16n32 partial via 4 n-tiles in registers (A fragments loaded once).
// W slice split hi/lo once; h staged + split per step. Partials reduced via
// SMEM, linear coalesced epilogue. Per-group (16 CTA) counter barrier.
__global__ __launch_bounds__(256, 1)
void rnn_kernel(const float* __restrict__ Whh,
                const float* __restrict__ bhh,
                float* __restrict__ out) {
    extern __shared__ float sm[];

    const int tid  = threadIdx.x;
    const int lane = tid & 31;
    const int wrp  = tid >> 5;           // 0..7 : k-slice [64*wrp, 64*wrp+64)
    const int gID  = lane >> 2;          // 0..7
    const int tig  = lane & 3;           // 0..3
    const int grp  = blockIdx.x >> 4;    // 0..7
    const int cCTA = blockIdx.x & 15;    // 0..15
    const int rowbase = grp * ROWS_PER_GROUP;
    const int colbase = cCTA * COLS_PER_CTA;

    // ---- one-time: split W slice (32 cols x 512 k) into bHi/bLo ----
    {
        const float4* wsrc = (const float4*)(Whh + (size_t)colbase * H_DIM);
#pragma unroll
        for (int i = 0; i < 16; i++) {       // 4096 float4 / 256 threads
            int f  = i * 256 + tid;
            int n  = f >> 7;                 // 0..31
            int c4 = f & 127;
            float4 v = wsrc[f];
            float4 hi, lo;
            hi.x = __uint_as_float(f2tf32(v.x)); lo.x = __uint_as_float(f2tf32(v.x - hi.x));
            hi.y = __uint_as_float(f2tf32(v.y)); lo.y = __uint_as_float(f2tf32(v.y - hi.y));
            hi.z = __uint_as_float(f2tf32(v.z)); lo.z = __uint_as_float(f2tf32(v.z - hi.z));
            hi.w = __uint_as_float(f2tf32(v.w)); lo.w = __uint_as_float(f2tf32(v.w - hi.w));
            *(float4*)&sm[BHI_OFF + n * APAD + c4 * 4] = hi;
            *(float4*)&sm[BLO_OFF + n * APAD + c4 * 4] = lo;
        }
    }
    const float biasv = bhh[colbase + (tid & 31)];
    __syncthreads();

    float* const hlast = out + (size_t)T_DIM * B_DIM * H_DIM;
    int* const cnt = &g_counts[grp * 128];

    // epilogue mapping: output o1 = tid -> (r = tid>>5, c = tid&31); o2 = o1 + 256
    const int er = tid >> 5;
    const int ec = tid & 31;
    const size_t ob1 = (size_t)(rowbase + er) * H_DIM + colbase + ec;
    const size_t ob2 = (size_t)(rowbase + er + 8) * H_DIM + colbase + ec;

    // MMA base indices
    const int aR0 = gID * APAD;
    const int aR1 = (gID + 8) * APAD;

    for (int t = 0; t < T_DIM; ++t) {
        // prefetch xp early
        const float xp1 = __ldcg(&g_xp[(size_t)t * B_DIM * H_DIM + ob1]);
        const float xp2 = __ldcg(&g_xp[(size_t)t * B_DIM * H_DIM + ob2]);

        float s1 = 0.0f, s2 = 0.0f;

        if (t > 0) {
            // ---- stage + split h (16 rows x 512) ----
            const float4* src = (const float4*)(out + (size_t)(t - 1) * B_DIM * H_DIM
                                                + (size_t)rowbase * H_DIM);
            float4 pre[8];
#pragma unroll
            for (int i = 0; i < 8; i++) pre[i] = __ldcg(src + i * 256 + tid);
#pragma unroll
            for (int i = 0; i < 8; i++) {
                int f  = i * 256 + tid;
                int r  = f >> 7;
                int c4 = f & 127;
                float4 v = pre[i];
                float4 hi, lo;
                hi.x = __uint_as_float(f2tf32(v.x)); lo.x = __uint_as_float(f2tf32(v.x - hi.x));
                hi.y = __uint_as_float(f2tf32(v.y)); lo.y = __uint_as_float(f2tf32(v.y - hi.y));
                hi.z = __uint_as_float(f2tf32(v.z)); lo.z = __uint_as_float(f2tf32(v.z - hi.z));
                hi.w = __uint_as_float(f2tf32(v.w)); lo.w = __uint_as_float(f2tf32(v.w - hi.w));
                *(float4*)&sm[AHI_OFF + r * APAD + c4 * 4] = hi;
                *(float4*)&sm[ALO_OFF + r * APAD + c4 * 4] = lo;
            }
            __syncthreads();

            // ---- MMA: warp k-slice, 4 n-tiles, 3 chains each ----
            float accHH[4][4], accHL[4][4], accLH[4][4];
#pragma unroll
            for (int n = 0; n < 4; n++)
#pragma unroll
                for (int j = 0; j < 4; j++) {
                    accHH[n][j] = 0.0f; accHL[n][j] = 0.0f; accLH[n][j] = 0.0f;
                }

            const int kb0 = wrp * 64;
#pragma unroll
            for (int kt = 0; kt < 8; kt++) {
                const int kb = kb0 + kt * 8;
                // A fragments (hi, lo)
                uint32_t ah0 = __float_as_uint(sm[AHI_OFF + aR0 + kb + tig]);
                uint32_t ah1 = __float_as_uint(sm[AHI_OFF + aR1 + kb + tig]);
                uint32_t ah2 = __float_as_uint(sm[AHI_OFF + aR0 + kb + tig + 4]);
                uint32_t ah3 = __float_as_uint(sm[AHI_OFF + aR1 + kb + tig + 4]);
                uint32_t al0 = __float_as_uint(sm[ALO_OFF + aR0 + kb + tig]);
                uint32_t al1 = __float_as_uint(sm[ALO_OFF + aR1 + kb + tig]);
                uint32_t al2 = __float_as_uint(sm[ALO_OFF + aR0 + kb + tig + 4]);
                uint32_t al3 = __float_as_uint(sm[ALO_OFF + aR1 + kb + tig + 4]);
#pragma unroll
                for (int n = 0; n < 4; n++) {
                    const int bR = (n * 8 + gID) * APAD;
                    uint32_t bh0 = __float_as_uint(sm[BHI_OFF + bR + kb + tig]);
                    uint32_t bh1 = __float_as_uint(sm[BHI_OFF + bR + kb + tig + 4]);
                    uint32_t bl0 = __float_as_uint(sm[BLO_OFF + bR + kb + tig]);
                    uint32_t bl1 = __float_as_uint(sm[BLO_OFF + bR + kb + tig + 4]);
                    mma_tf32(accHH[n], ah0, ah1, ah2, ah3, bh0, bh1);
                    mma_tf32(accHL[n], ah0, ah1, ah2, ah3, bl0, bl1);
                    mma_tf32(accLH[n], al0, al1, al2, al3, bh0, bh1);
                }
            }

            // ---- write partials to red[wrp][16][33] ----
            float* rw = &sm[RED_OFF + wrp * RED_WSTRIDE];
#pragma unroll
            for (int n = 0; n < 4; n++) {
                float m0 = accHH[n][0] + accHL[n][0] + accLH[n][0];
                float m1 = accHH[n][1] + accHL[n][1] + accLH[n][1];
                float m2 = accHH[n][2] + accHL[n][2] + accLH[n][2];
                float m3 = accHH[n][3] + accHL[n][3] + accLH[n][3];
                const int c = n * 8 + 2 * tig;
                rw[gID * 33 + c]           = m0;
                rw[gID * 33 + c + 1]       = m1;
                rw[(gID + 8) * 33 + c]     = m2;
                rw[(gID + 8) * 33 + c + 1] = m3;
            }
            __syncthreads();

            // ---- reduce 8 partials for this thread's 2 outputs ----
            const int rbase1 = er * 33 + ec;
            const int rbase2 = (er + 8) * 33 + ec;
#pragma unroll
            for (int w = 0; w < 8; w++) {
                s1 += sm[RED_OFF + w * RED_WSTRIDE + rbase1];
                s2 += sm[RED_OFF + w * RED_WSTRIDE + rbase2];
            }
        }

        // ---- epilogue: tanh + coalesced stores ----
        float v1 = tanhf(s1 + xp1 + biasv);
        float v2 = tanhf(s2 + xp2 + biasv);
        float* hout = out + (size_t)t * B_DIM * H_DIM;
        hout[ob1] = v1;
        hout[ob2] = v2;
        if (t == T_DIM - 1) { hlast[ob1] = v1; hlast[ob2] = v2; }

        // ---- per-group barrier (16 arrivals) ----
        if (t < T_DIM - 1) {
            __syncthreads();
            if (tid == 0) {
                red_rel_add(cnt, 1);
                const int target = CTAS_PER_GROUP * (t + 1);
                while (ld_acq(cnt) < target) { __nanosleep(16); }
            }
            __syncthreads();
        }
    }
}

// ---------------- launch ----------------
extern "C" void kernel_launch(void* const* d_in, const int* in_sizes, int n_in,
                              void* d_out, int out_size) {
    const float* x    = (const float*)d_in[0];
    const float* W_ih = (const float*)d_in[1];
    const float* b_ih = (const float*)d_in[2];
    const float* W_hh = (const float*)d_in[3];
    const float* b_hh = (const float*)d_in[4];
    float* out = (float*)d_out;

    cudaFuncSetAttribute(rnn_kernel, cudaFuncAttributeMaxDynamicSharedMemorySize,
                         RNN_SMEM_BYTES);

    xp_kernel<<<dim3(R_DIM / 64, H_DIM / 64), 256>>>(x, W_ih, b_ih);
    rnn_kernel<<<128, 256, RNN_SMEM_BYTES>>>(W_hh, b_hh, out);
}